// round 11
// baseline (speedup 1.0000x reference)
#include <cuda_runtime.h>
#include <cuda_fp16.h>
#include <cstdint>
#include <math.h>

// ---------------- problem constants ----------------
#define BATCH    64
#define SEQ      32
#define M_TOTAL  2048      // B*T
#define K_TOTAL  32768     // D*H*W
#define N_TOTAL  512       // 4*D
#define N_EXP    9
#define SPLITS   4
#define KCH      64        // K per chunk
#define NCHUNK   128       // chunks per split: 32768/4/64
#define NSTAGE   3
#define NTHREADS 512       // 16 warps: 4 (m) x 4 (n), warp tile 32x64

// A stage: 128 rows x 288B (64 fp32 + 32B pad)  = 36864
// B stage: 256 rows x 128B (64 fp16, SW128)     = 32768
#define A_STAGE_BYTES 36864
#define STAGE_BYTES   (A_STAGE_BYTES + 32768)
#define SMEM_BYTES    (NSTAGE * STAGE_BYTES + 1024)

// scratch (no allocation allowed -> __device__ globals)
__device__ __half g_Wp[(size_t)N_TOTAL * K_TOTAL];                 // 32 MB fp16, [c][k']
__device__ float  g_scratch[(size_t)SPLITS * M_TOTAL * N_TOTAL];   // 16 MB split-K partials
__device__ float  g_loadpart[BATCH * N_EXP];

// ---------------- helpers ----------------
__device__ __forceinline__ uint32_t smem_u32(const void* p) {
    uint32_t a;
    asm("{ .reg .u64 t; cvta.to.shared.u64 t, %1; cvt.u32.u64 %0, t; }" : "=r"(a) : "l"(p));
    return a;
}
#define SWZ(off) ((off) ^ (((off) >> 3) & 0x70))

__device__ __forceinline__ void cpasync16(uint32_t daddr, const void* src) {
    asm volatile("cp.async.cg.shared.global [%0], [%1], 16;" :: "r"(daddr), "l"(src) : "memory");
}
#define CP_COMMIT() asm volatile("cp.async.commit_group;" ::: "memory")
#define CP_WAIT1()  asm volatile("cp.async.wait_group 1;" ::: "memory")

#define LDSM4(r, addr) \
    asm volatile("ldmatrix.sync.aligned.m8n8.x4.shared.b16 {%0,%1,%2,%3}, [%4];" \
                 : "=r"((r)[0]), "=r"((r)[1]), "=r"((r)[2]), "=r"((r)[3]) : "r"(addr))

// fp16-accumulate MMA: D(f16x2 x2) = A*B + D
#define MMA16816H(d, a, b0, b1) \
    asm volatile("mma.sync.aligned.m16n8k16.row.col.f16.f16.f16.f16 " \
                 "{%0,%1}, {%2,%3,%4,%5}, {%6,%7}, {%0,%1};" \
                 : "+r"((d)[0]), "+r"((d)[1]) \
                 : "r"((a)[0]), "r"((a)[1]), "r"((a)[2]), "r"((a)[3]), "r"(b0), "r"(b1))

__device__ __forceinline__ uint32_t cvt_h2(float lo, float hi) {
    uint32_t r;
    asm("cvt.rn.f16x2.f32 %0, %1, %2;" : "=r"(r) : "f"(hi), "f"(lo));
    return r;
}
__device__ __forceinline__ uint32_t pack2h(float a, float b) { return cvt_h2(a, b); }

// ---------------- no-op kernel (shifts ncu -s window onto k_gemm) ----------------
__global__ void k_nop() {}

// ---------------- kernel 1: permute + convert conv_w -> g_Wp fp16 ----------------
// Wp[c][(h*16+w)*128 + d] = conv_w[c][d][h][w];  d = dblk*16 + j2, dblk in [0,8)
__global__ void __launch_bounds__(256) k_permW(const float* __restrict__ w) {
    int c = blockIdx.x, dblk = blockIdx.y, tid = threadIdx.x;   // grid (512, 8); tid = hw
    const float* src = w + (size_t)c * K_TOTAL + (size_t)dblk * 16 * 256 + tid;
    uint32_t pk[8];
#pragma unroll
    for (int j = 0; j < 8; j++)
        pk[j] = pack2h(src[(2 * j) * 256], src[(2 * j + 1) * 256]);
    __half* dst = g_Wp + (size_t)c * K_TOTAL + (size_t)tid * 128 + dblk * 16;
    reinterpret_cast<uint4*>(dst)[0] = make_uint4(pk[0], pk[1], pk[2], pk[3]);
    reinterpret_cast<uint4*>(dst)[1] = make_uint4(pk[4], pk[5], pk[6], pk[7]);
}

// ---------------- kernel 2: HMMA split-K GEMM (fp16 accumulate + fp32 masters) ----------------
// grid (16 m-tiles, 2 n-tiles, 4 splits), 512 thr. CTA tile M=128 N=256, K=8192.
__device__ __forceinline__ void load_stage(uint32_t sbase, const float* __restrict__ x,
                                           int m0, int n0, int k0, int tid) {
    // A: 128 rows x 64 fp32, padded rows of 288B  (2048 x 16B)
#pragma unroll
    for (int i = 0; i < 4; i++) {
        int id = tid + i * NTHREADS;         // 0..2047
        int row = id >> 4, seg = id & 15;    // seg: 16B = 4 floats
        cpasync16(sbase + (uint32_t)row * 288u + (uint32_t)seg * 16u,
                  x + (size_t)(m0 + row) * K_TOTAL + k0 + seg * 4);
    }
    // B: 256 rows x 128B fp16, SW128  (2048 x 16B)
    uint32_t bb = sbase + A_STAGE_BYTES;
#pragma unroll
    for (int i = 0; i < 4; i++) {
        int id = tid + i * NTHREADS;         // 0..2047
        int row = id >> 3, seg = id & 7;     // seg: 16B = 8 halves
        cpasync16(bb + SWZ((uint32_t)row * 128u + (uint32_t)seg * 16u),
                  g_Wp + (size_t)(n0 + row) * K_TOTAL + k0 + seg * 8);
    }
    CP_COMMIT();
}

__global__ void __launch_bounds__(NTHREADS, 1) k_gemm(const float* __restrict__ x) {
    extern __shared__ char sm[];
    uint32_t ubase = (smem_u32(sm) + 1023u) & ~1023u;
    char* cbase = sm + (ubase - smem_u32(sm));

    const int tid = threadIdx.x, lane = tid & 31, wid = tid >> 5;
    const int warp_m = wid & 3, warp_n = wid >> 2;     // 4 x 4 warps, warp tile 32x64
    const int m0 = blockIdx.x * 128, n0 = blockIdx.y * 256;
    const int split = blockIdx.z;
    const int kbase = split * (K_TOTAL / SPLITS);

    float acc[2][8][4];        // fp32 masters
    uint32_t h[2][8][2];       // fp16x2 working accumulators (K=128 window)
#pragma unroll
    for (int i = 0; i < 2; i++)
#pragma unroll
        for (int j = 0; j < 8; j++) {
#pragma unroll
            for (int q = 0; q < 4; q++) acc[i][j][q] = 0.f;
            h[i][j][0] = 0u; h[i][j][1] = 0u;
        }

    load_stage(ubase + 0 * STAGE_BYTES, x, m0, n0, kbase, tid);
    load_stage(ubase + 1 * STAGE_BYTES, x, m0, n0, kbase + KCH, tid);

    for (int c = 0; c < NCHUNK; ++c) {
        CP_WAIT1();
        __syncthreads();
        if (c + 2 < NCHUNK)
            load_stage(ubase + ((c + 2) % NSTAGE) * STAGE_BYTES, x, m0, n0,
                       kbase + (c + 2) * KCH, tid);
        else
            CP_COMMIT();   // keep group count constant

        uint32_t As = ubase + (c % NSTAGE) * STAGE_BYTES;
        const char* Ap = cbase + (size_t)((c % NSTAGE) * STAGE_BYTES);
        uint32_t Bs = As + A_STAGE_BYTES;

#pragma unroll
        for (int ks = 0; ks < 4; ks++) {
            // B fragments for this k16 step: 4 x ldmatrix.x4 (each = n16)
            uint32_t b[4][4];
#pragma unroll
            for (int nj = 0; nj < 4; nj++) {
                uint32_t row = (uint32_t)(warp_n * 64 + nj * 16 + ((lane >> 4) & 1) * 8 + (lane & 7));
                uint32_t colb = (uint32_t)(ks * 32 + ((lane >> 3) & 1) * 16);
                LDSM4(b[nj], Bs + SWZ(row * 128u + colb));
            }
#pragma unroll
            for (int mi = 0; mi < 2; mi++) {
                int g = warp_m * 32 + mi * 16 + (lane >> 2);
                int k = ks * 16 + 2 * (lane & 3);
                const float2 p0 = *reinterpret_cast<const float2*>(Ap + (size_t)g * 288 + (size_t)k * 4);
                const float2 p1 = *reinterpret_cast<const float2*>(Ap + (size_t)(g + 8) * 288 + (size_t)k * 4);
                const float2 p2 = *reinterpret_cast<const float2*>(Ap + (size_t)g * 288 + (size_t)(k + 8) * 4);
                const float2 p3 = *reinterpret_cast<const float2*>(Ap + (size_t)(g + 8) * 288 + (size_t)(k + 8) * 4);
                uint32_t a[4];
                a[0] = cvt_h2(p0.x, p0.y);
                a[1] = cvt_h2(p1.x, p1.y);
                a[2] = cvt_h2(p2.x, p2.y);
                a[3] = cvt_h2(p3.x, p3.y);
#pragma unroll
                for (int nj = 0; nj < 4; nj++) {
                    MMA16816H(h[mi][2 * nj],     a, b[nj][0], b[nj][1]);
                    MMA16816H(h[mi][2 * nj + 1], a, b[nj][2], b[nj][3]);
                }
            }
        }

        // promote fp16 window -> fp32 masters every 2 chunks (K=128 per window)
        if ((c & 1) == 1) {
#pragma unroll
            for (int mi = 0; mi < 2; mi++)
#pragma unroll
                for (int ni = 0; ni < 8; ni++) {
                    float2 f0 = __half22float2(*reinterpret_cast<__half2*>(&h[mi][ni][0]));
                    float2 f1 = __half22float2(*reinterpret_cast<__half2*>(&h[mi][ni][1]));
                    acc[mi][ni][0] += f0.x; acc[mi][ni][1] += f0.y;
                    acc[mi][ni][2] += f1.x; acc[mi][ni][3] += f1.y;
                    h[mi][ni][0] = 0u; h[mi][ni][1] = 0u;
                }
        }
    }

    // epilogue: write partials to g_scratch[split][m][n]
    float* dst = g_scratch + (size_t)split * M_TOTAL * N_TOTAL;
#pragma unroll
    for (int mi = 0; mi < 2; mi++) {
        int row = m0 + warp_m * 32 + mi * 16 + (lane >> 2);
#pragma unroll
        for (int ni = 0; ni < 8; ni++) {
            int col = n0 + warp_n * 64 + (ni >> 1) * 16 + (ni & 1) * 8 + 2 * (lane & 3);
            *reinterpret_cast<float2*>(dst + (size_t)row * N_TOTAL + col) =
                make_float2(acc[mi][ni][0], acc[mi][ni][1]);
            *reinterpret_cast<float2*>(dst + (size_t)(row + 8) * N_TOTAL + col) =
                make_float2(acc[mi][ni][2], acc[mi][ni][3]);
        }
    }
}

// ---------------- kernel 3: per-batch gating ----------------
__global__ void __launch_bounds__(256) k_gate(
    const float* __restrict__ conv_b, const float* __restrict__ w_gate,
    const float* __restrict__ w_noise, const float* __restrict__ noisev,
    const int* __restrict__ training, float* __restrict__ out, int out_size) {
    extern __shared__ float feat[];            // 32 x 512
    __shared__ float trigc[16][32];
    __shared__ float trigs[16][32];
    __shared__ float wred[16][8];
    __shared__ float amp_s[16];
    int b = blockIdx.x, tid = threadIdx.x;

    for (int idx = tid; idx < 512; idx += 256) {
        int fi = idx >> 5, t = idx & 31;
        float s, c;
        sincospif((float)((fi + 1) * t) / 16.0f, &s, &c);    // angle = 2*pi*f*t/32
        trigc[fi][t] = c;
        trigs[fi][t] = s;
    }

    for (int idx = tid; idx < 32 * 512; idx += 256) {
        int t = idx >> 9, c = idx & 511;
        const float* p = g_scratch + (size_t)(b * 32 + t) * N_TOTAL + c;
        float s = conv_b[c];
#pragma unroll
        for (int sp = 0; sp < SPLITS; sp++) s += p[(size_t)sp * M_TOTAL * N_TOTAL];
        feat[idx] = s;
    }
    __syncthreads();

    float part[16];
#pragma unroll
    for (int f = 0; f < 16; f++) part[f] = 0.f;
#pragma unroll
    for (int cc = 0; cc < 2; cc++) {
        int ch = tid * 2 + cc;
        float v[32];
#pragma unroll
        for (int t = 0; t < 32; t++) v[t] = feat[t * 512 + ch];
#pragma unroll
        for (int f = 0; f < 16; f++) {
            float re = 0.f, im = 0.f;
#pragma unroll
            for (int t = 0; t < 32; t++) {
                re += v[t] * trigc[f][t];
                im += v[t] * trigs[f][t];
            }
            part[f] += sqrtf(re * re + im * im);
        }
    }
    int lane = tid & 31, w = tid >> 5;
#pragma unroll
    for (int f = 0; f < 16; f++) {
        float xv = part[f];
        for (int o = 16; o; o >>= 1) xv += __shfl_down_sync(0xFFFFFFFFu, xv, o);
        if (lane == 0) wred[f][w] = xv;
    }
    __syncthreads();
    if (tid < 16) {
        float s = 0.f;
#pragma unroll
        for (int ww = 0; ww < 8; ww++) s += wred[tid][ww];
        amp_s[tid] = s * (0.17677669529663687f / 512.0f);   // ortho 1/sqrt(32), mean over 512
    }
    __syncthreads();

    if (tid == 0) {
        float amp[16];
        for (int f = 0; f < 16; f++) amp[f] = amp_s[f];
        int tr = training ? (training[0] != 0) : 1;
        float clean[9], lg[9], sd[9];
        for (int e = 0; e < 9; e++) {
            float cg = 0.f, cn = 0.f;
            for (int f = 0; f < 16; f++) {
                cg += amp[f] * w_gate[f * 9 + e];
                cn += amp[f] * w_noise[f * 9 + e];
            }
            clean[e] = cg;
            float sp = (cn > 20.f) ? cn : log1pf(expf(cn));
            sd[e] = sp + 0.01f;
            lg[e] = tr ? (cg + noisev[b * 9 + e] * sd[e]) : cg;
        }
        int i0 = 0, i1 = -1, i2 = -1;
        float v0 = -1e30f, v1 = -1e30f, v2 = -1e30f;
        for (int e = 0; e < 9; e++) if (lg[e] > v0) { v0 = lg[e]; i0 = e; }
        for (int e = 0; e < 9; e++) if (e != i0 && lg[e] > v1) { v1 = lg[e]; i1 = e; }
        for (int e = 0; e < 9; e++) if (e != i0 && e != i1 && lg[e] > v2) { v2 = lg[e]; i2 = e; }
        float e1 = expf(v1 - v0);
        float inv = 1.f / (1.f + e1);
        if (b * 9 + 9 <= out_size) {
            for (int e = 0; e < 9; e++) out[b * 9 + e] = 0.f;
            out[b * 9 + i0] = inv;
            out[b * 9 + i1] = e1 * inv;
        }
        if (tr) {
            for (int e = 0; e < 9; e++) {
                float thr = (lg[e] > v2) ? v2 : v1;
                float xn = (clean[e] - thr) / sd[e];
                g_loadpart[b * 9 + e] = 0.5f * erfcf(-xn * 0.7071067811865476f);
            }
        } else {
            for (int e = 0; e < 9; e++)
                g_loadpart[b * 9 + e] = (e == i0 || e == i1) ? 1.f : 0.f;
        }
        (void)i2;
    }
}

// ---------------- kernel 4: deterministic load reduction ----------------
__global__ void k_load(float* __restrict__ out, int out_size) {
    int e = threadIdx.x;
    if (e < N_EXP && BATCH * N_EXP + e < out_size) {
        float s = 0.f;
        for (int b = 0; b < BATCH; b++) s += g_loadpart[b * N_EXP + e];
        out[BATCH * N_EXP + e] = s;
    }
}

// ---------------- launch ----------------
extern "C" void kernel_launch(void* const* d_in, const int* in_sizes, int n_in,
                              void* d_out, int out_size) {
    const float* x       = (const float*)d_in[0];
    const float* conv_w  = (const float*)d_in[1];
    const float* conv_b  = (const float*)d_in[2];
    const float* w_gate  = (const float*)d_in[3];
    const float* w_noise = (const float*)d_in[4];
    const float* noisev  = (const float*)d_in[5];
    const int*   training = (n_in > 6) ? (const int*)d_in[6] : nullptr;
    float* out = (float*)d_out;

    cudaFuncSetAttribute(k_gemm, cudaFuncAttributeMaxDynamicSharedMemorySize, SMEM_BYTES);
    cudaFuncSetAttribute(k_gate, cudaFuncAttributeMaxDynamicSharedMemorySize, 65536);

    k_permW<<<dim3(512, 8), 256>>>(conv_w);
    k_nop<<<1, 32>>>();   // ncu -s alignment: put k_gemm at global launch #6
    k_nop<<<1, 32>>>();
    k_gemm<<<dim3(16, 2, SPLITS), NTHREADS, SMEM_BYTES>>>(x);
    k_gate<<<BATCH, 256, 65536>>>(conv_b, w_gate, w_noise, noisev, training, out, out_size);
    k_load<<<1, 32>>>(out, out_size);
}

// round 12
// speedup vs baseline: 1.0777x; 1.0777x over previous
#include <cuda_runtime.h>
#include <cuda_fp16.h>
#include <cstdint>
#include <math.h>

// ---------------- problem constants ----------------
#define BATCH    64
#define SEQ      32
#define M_TOTAL  2048      // B*T
#define K_TOTAL  32768     // D*H*W
#define N_TOTAL  512       // 4*D
#define N_EXP    9
#define SPLITS   4
#define KCH      64        // K per chunk
#define NCHUNK   128       // chunks per split: 32768/4/64
#define NSTAGE   3
#define NTHREADS 512       // 16 warps: 4 (m) x 4 (n), warp tile 32x64

// A stage: 128 rows x 128B (64 fp16, SW128) = 16384
// B stage: 256 rows x 128B (64 fp16, SW128) = 32768
#define A_STAGE_BYTES 16384
#define STAGE_BYTES   (A_STAGE_BYTES + 32768)
#define SMEM_BYTES    (NSTAGE * STAGE_BYTES + 1024)

// scratch (no allocation allowed -> __device__ globals)
__device__ __half g_Wp[(size_t)N_TOTAL * K_TOTAL];                 // 32 MB fp16, [c][k']
__device__ __half g_Xh[(size_t)M_TOTAL * K_TOTAL];                 // 128 MB fp16 x
__device__ float  g_scratch[(size_t)SPLITS * M_TOTAL * N_TOTAL];   // 16 MB split-K partials
__device__ float  g_loadpart[BATCH * N_EXP];

// ---------------- helpers ----------------
__device__ __forceinline__ uint32_t smem_u32(const void* p) {
    uint32_t a;
    asm("{ .reg .u64 t; cvta.to.shared.u64 t, %1; cvt.u32.u64 %0, t; }" : "=r"(a) : "l"(p));
    return a;
}
#define SWZ(off) ((off) ^ (((off) >> 3) & 0x70))

__device__ __forceinline__ void cpasync16(uint32_t daddr, const void* src) {
    asm volatile("cp.async.cg.shared.global [%0], [%1], 16;" :: "r"(daddr), "l"(src) : "memory");
}
#define CP_COMMIT() asm volatile("cp.async.commit_group;" ::: "memory")
#define CP_WAIT1()  asm volatile("cp.async.wait_group 1;" ::: "memory")

#define LDSM4(r, addr) \
    asm volatile("ldmatrix.sync.aligned.m8n8.x4.shared.b16 {%0,%1,%2,%3}, [%4];" \
                 : "=r"((r)[0]), "=r"((r)[1]), "=r"((r)[2]), "=r"((r)[3]) : "r"(addr))

#define MMA16816(d, a, b0, b1) \
    asm volatile("mma.sync.aligned.m16n8k16.row.col.f32.f16.f16.f32 " \
                 "{%0,%1,%2,%3}, {%4,%5,%6,%7}, {%8,%9}, {%0,%1,%2,%3};" \
                 : "+f"((d)[0]), "+f"((d)[1]), "+f"((d)[2]), "+f"((d)[3]) \
                 : "r"((a)[0]), "r"((a)[1]), "r"((a)[2]), "r"((a)[3]), "r"(b0), "r"(b1))

__device__ __forceinline__ uint32_t pack2h(float a, float b) {
    uint32_t r;
    asm("cvt.rn.f16x2.f32 %0, %1, %2;" : "=r"(r) : "f"(b), "f"(a));
    return r;
}

// ---------------- no-op kernel (shifts ncu -s window onto k_gemm) ----------------
__global__ void k_nop() {}

// ---------------- kernel 0: x fp32 -> fp16 (same layout) ----------------
__global__ void __launch_bounds__(256) k_convX(const float* __restrict__ x) {
    size_t base = ((size_t)blockIdx.x * 256 + threadIdx.x) * 8;
    float4 a = *reinterpret_cast<const float4*>(x + base);
    float4 b = *reinterpret_cast<const float4*>(x + base + 4);
    uint4 v;
    v.x = pack2h(a.x, a.y); v.y = pack2h(a.z, a.w);
    v.z = pack2h(b.x, b.y); v.w = pack2h(b.z, b.w);
    *reinterpret_cast<uint4*>(g_Xh + base) = v;
}

// ---------------- kernel 1: permute + convert conv_w -> g_Wp fp16 ----------------
// Wp[c][(h*16+w)*128 + d] = conv_w[c][d][h][w];  d = dblk*16 + j2, dblk in [0,8)
__global__ void __launch_bounds__(256) k_permW(const float* __restrict__ w) {
    int c = blockIdx.x, dblk = blockIdx.y, tid = threadIdx.x;   // grid (512, 8); tid = hw
    const float* src = w + (size_t)c * K_TOTAL + (size_t)dblk * 16 * 256 + tid;
    uint32_t pk[8];
#pragma unroll
    for (int j = 0; j < 8; j++)
        pk[j] = pack2h(src[(2 * j) * 256], src[(2 * j + 1) * 256]);
    __half* dst = g_Wp + (size_t)c * K_TOTAL + (size_t)tid * 128 + dblk * 16;
    reinterpret_cast<uint4*>(dst)[0] = make_uint4(pk[0], pk[1], pk[2], pk[3]);
    reinterpret_cast<uint4*>(dst)[1] = make_uint4(pk[4], pk[5], pk[6], pk[7]);
}

// ---------------- kernel 2: HMMA split-K GEMM (all-fp16 operands, ldmatrix A+B) ----
// grid (16 m-tiles, 2 n-tiles, 4 splits), 512 thr. CTA tile M=128 N=256, K=8192.
__device__ __forceinline__ void load_stage(uint32_t sbase, int m0, int n0, int k0, int tid) {
    // A: 128 rows x 128B fp16, SW128  (1024 x 16B)
#pragma unroll
    for (int i = 0; i < 2; i++) {
        int id = tid + i * NTHREADS;         // 0..1023
        int row = id >> 3, seg = id & 7;     // seg: 16B = 8 halves
        cpasync16(sbase + SWZ((uint32_t)row * 128u + (uint32_t)seg * 16u),
                  g_Xh + (size_t)(m0 + row) * K_TOTAL + k0 + seg * 8);
    }
    // B: 256 rows x 128B fp16, SW128  (2048 x 16B)
    uint32_t bb = sbase + A_STAGE_BYTES;
#pragma unroll
    for (int i = 0; i < 4; i++) {
        int id = tid + i * NTHREADS;         // 0..2047
        int row = id >> 3, seg = id & 7;
        cpasync16(bb + SWZ((uint32_t)row * 128u + (uint32_t)seg * 16u),
                  g_Wp + (size_t)(n0 + row) * K_TOTAL + k0 + seg * 8);
    }
    CP_COMMIT();
}

__global__ void __launch_bounds__(NTHREADS, 1) k_gemm() {
    extern __shared__ char sm[];
    uint32_t ubase = (smem_u32(sm) + 1023u) & ~1023u;

    const int tid = threadIdx.x, lane = tid & 31, wid = tid >> 5;
    const int warp_m = wid & 3, warp_n = wid >> 2;     // 4 x 4 warps, warp tile 32x64
    const int m0 = blockIdx.x * 128, n0 = blockIdx.y * 256;
    const int split = blockIdx.z;
    const int kbase = split * (K_TOTAL / SPLITS);

    float acc[2][8][4];
#pragma unroll
    for (int i = 0; i < 2; i++)
#pragma unroll
        for (int j = 0; j < 8; j++)
#pragma unroll
            for (int q = 0; q < 4; q++) acc[i][j][q] = 0.f;

    load_stage(ubase + 0 * STAGE_BYTES, m0, n0, kbase, tid);
    load_stage(ubase + 1 * STAGE_BYTES, m0, n0, kbase + KCH, tid);

    // ldmatrix lane addressing (constant per thread):
    // A fragment: r0=(m0-7,k0-7) r1=(m+8,k0-7) r2=(m0-7,k8-15) r3=(m+8,k8-15)
    const uint32_t a_row = (uint32_t)(warp_m * 32 + ((lane >> 3) & 1) * 8 + (lane & 7));
    const uint32_t a_colb = (uint32_t)(((lane >> 4) & 1) * 16);
    // B fragment: r0=(n0-7,k0-7) r1=(n0-7,k8-15) r2=(n+8,k0-7) r3=(n+8,k8-15)
    const uint32_t b_row = (uint32_t)(warp_n * 64 + ((lane >> 4) & 1) * 8 + (lane & 7));
    const uint32_t b_colb = (uint32_t)(((lane >> 3) & 1) * 16);

    for (int c = 0; c < NCHUNK; ++c) {
        CP_WAIT1();
        __syncthreads();
        if (c + 2 < NCHUNK)
            load_stage(ubase + ((c + 2) % NSTAGE) * STAGE_BYTES, m0, n0,
                       kbase + (c + 2) * KCH, tid);
        else
            CP_COMMIT();   // keep group count constant

        uint32_t As = ubase + (c % NSTAGE) * STAGE_BYTES;
        uint32_t Bs = As + A_STAGE_BYTES;

#pragma unroll
        for (int ks = 0; ks < 4; ks++) {
            uint32_t b[4][4];
#pragma unroll
            for (int nj = 0; nj < 4; nj++)
                LDSM4(b[nj], Bs + SWZ((b_row + nj * 16) * 128u + (uint32_t)(ks * 32) + b_colb));
            uint32_t a2[2][4];
#pragma unroll
            for (int mi = 0; mi < 2; mi++)
                LDSM4(a2[mi], As + SWZ((a_row + mi * 16) * 128u + (uint32_t)(ks * 32) + a_colb));
#pragma unroll
            for (int mi = 0; mi < 2; mi++)
#pragma unroll
                for (int nj = 0; nj < 4; nj++) {
                    MMA16816(acc[mi][2 * nj],     a2[mi], b[nj][0], b[nj][1]);
                    MMA16816(acc[mi][2 * nj + 1], a2[mi], b[nj][2], b[nj][3]);
                }
        }
    }

    // epilogue: write partials to g_scratch[split][m][n]
    float* dst = g_scratch + (size_t)split * M_TOTAL * N_TOTAL;
#pragma unroll
    for (int mi = 0; mi < 2; mi++) {
        int row = m0 + warp_m * 32 + mi * 16 + (lane >> 2);
#pragma unroll
        for (int ni = 0; ni < 8; ni++) {
            int col = n0 + warp_n * 64 + (ni >> 1) * 16 + (ni & 1) * 8 + 2 * (lane & 3);
            *reinterpret_cast<float2*>(dst + (size_t)row * N_TOTAL + col) =
                make_float2(acc[mi][ni][0], acc[mi][ni][1]);
            *reinterpret_cast<float2*>(dst + (size_t)(row + 8) * N_TOTAL + col) =
                make_float2(acc[mi][ni][2], acc[mi][ni][3]);
        }
    }
}

// ---------------- kernel 3: per-batch gating ----------------
__global__ void __launch_bounds__(256) k_gate(
    const float* __restrict__ conv_b, const float* __restrict__ w_gate,
    const float* __restrict__ w_noise, const float* __restrict__ noisev,
    const int* __restrict__ training, float* __restrict__ out, int out_size) {
    extern __shared__ float feat[];            // 32 x 512
    __shared__ float trigc[16][32];
    __shared__ float trigs[16][32];
    __shared__ float wred[16][8];
    __shared__ float amp_s[16];
    int b = blockIdx.x, tid = threadIdx.x;

    for (int idx = tid; idx < 512; idx += 256) {
        int fi = idx >> 5, t = idx & 31;
        float s, c;
        sincospif((float)((fi + 1) * t) / 16.0f, &s, &c);    // angle = 2*pi*f*t/32
        trigc[fi][t] = c;
        trigs[fi][t] = s;
    }

    for (int idx = tid; idx < 32 * 512; idx += 256) {
        int t = idx >> 9, c = idx & 511;
        const float* p = g_scratch + (size_t)(b * 32 + t) * N_TOTAL + c;
        float s = conv_b[c];
#pragma unroll
        for (int sp = 0; sp < SPLITS; sp++) s += p[(size_t)sp * M_TOTAL * N_TOTAL];
        feat[idx] = s;
    }
    __syncthreads();

    float part[16];
#pragma unroll
    for (int f = 0; f < 16; f++) part[f] = 0.f;
#pragma unroll
    for (int cc = 0; cc < 2; cc++) {
        int ch = tid * 2 + cc;
        float v[32];
#pragma unroll
        for (int t = 0; t < 32; t++) v[t] = feat[t * 512 + ch];
#pragma unroll
        for (int f = 0; f < 16; f++) {
            float re = 0.f, im = 0.f;
#pragma unroll
            for (int t = 0; t < 32; t++) {
                re += v[t] * trigc[f][t];
                im += v[t] * trigs[f][t];
            }
            part[f] += sqrtf(re * re + im * im);
        }
    }
    int lane = tid & 31, w = tid >> 5;
#pragma unroll
    for (int f = 0; f < 16; f++) {
        float xv = part[f];
        for (int o = 16; o; o >>= 1) xv += __shfl_down_sync(0xFFFFFFFFu, xv, o);
        if (lane == 0) wred[f][w] = xv;
    }
    __syncthreads();
    if (tid < 16) {
        float s = 0.f;
#pragma unroll
        for (int ww = 0; ww < 8; ww++) s += wred[tid][ww];
        amp_s[tid] = s * (0.17677669529663687f / 512.0f);   // ortho 1/sqrt(32), mean over 512
    }
    __syncthreads();

    if (tid == 0) {
        float amp[16];
        for (int f = 0; f < 16; f++) amp[f] = amp_s[f];
        int tr = training ? (training[0] != 0) : 1;
        float clean[9], lg[9], sd[9];
        for (int e = 0; e < 9; e++) {
            float cg = 0.f, cn = 0.f;
            for (int f = 0; f < 16; f++) {
                cg += amp[f] * w_gate[f * 9 + e];
                cn += amp[f] * w_noise[f * 9 + e];
            }
            clean[e] = cg;
            float sp = (cn > 20.f) ? cn : log1pf(expf(cn));
            sd[e] = sp + 0.01f;
            lg[e] = tr ? (cg + noisev[b * 9 + e] * sd[e]) : cg;
        }
        int i0 = 0, i1 = -1, i2 = -1;
        float v0 = -1e30f, v1 = -1e30f, v2 = -1e30f;
        for (int e = 0; e < 9; e++) if (lg[e] > v0) { v0 = lg[e]; i0 = e; }
        for (int e = 0; e < 9; e++) if (e != i0 && lg[e] > v1) { v1 = lg[e]; i1 = e; }
        for (int e = 0; e < 9; e++) if (e != i0 && e != i1 && lg[e] > v2) { v2 = lg[e]; i2 = e; }
        float e1 = expf(v1 - v0);
        float inv = 1.f / (1.f + e1);
        if (b * 9 + 9 <= out_size) {
            for (int e = 0; e < 9; e++) out[b * 9 + e] = 0.f;
            out[b * 9 + i0] = inv;
            out[b * 9 + i1] = e1 * inv;
        }
        if (tr) {
            for (int e = 0; e < 9; e++) {
                float thr = (lg[e] > v2) ? v2 : v1;
                float xn = (clean[e] - thr) / sd[e];
                g_loadpart[b * 9 + e] = 0.5f * erfcf(-xn * 0.7071067811865476f);
            }
        } else {
            for (int e = 0; e < 9; e++)
                g_loadpart[b * 9 + e] = (e == i0 || e == i1) ? 1.f : 0.f;
        }
        (void)i2;
    }
}

// ---------------- kernel 4: deterministic load reduction ----------------
__global__ void k_load(float* __restrict__ out, int out_size) {
    int e = threadIdx.x;
    if (e < N_EXP && BATCH * N_EXP + e < out_size) {
        float s = 0.f;
        for (int b = 0; b < BATCH; b++) s += g_loadpart[b * N_EXP + e];
        out[BATCH * N_EXP + e] = s;
    }
}

// ---------------- launch ----------------
extern "C" void kernel_launch(void* const* d_in, const int* in_sizes, int n_in,
                              void* d_out, int out_size) {
    const float* x       = (const float*)d_in[0];
    const float* conv_w  = (const float*)d_in[1];
    const float* conv_b  = (const float*)d_in[2];
    const float* w_gate  = (const float*)d_in[3];
    const float* w_noise = (const float*)d_in[4];
    const float* noisev  = (const float*)d_in[5];
    const int*   training = (n_in > 6) ? (const int*)d_in[6] : nullptr;
    float* out = (float*)d_out;

    cudaFuncSetAttribute(k_gemm, cudaFuncAttributeMaxDynamicSharedMemorySize, SMEM_BYTES);
    cudaFuncSetAttribute(k_gate, cudaFuncAttributeMaxDynamicSharedMemorySize, 65536);

    k_permW<<<dim3(512, 8), 256>>>(conv_w);
    k_convX<<<32768, 256>>>(x);
    k_nop<<<1, 32>>>();   // ncu -s alignment: put k_gemm at global launch #6
    k_gemm<<<dim3(16, 2, SPLITS), NTHREADS, SMEM_BYTES>>>();
    k_gate<<<BATCH, 256, 65536>>>(conv_b, w_gate, w_noise, noisev, training, out, out_size);
    k_load<<<1, 32>>>(out, out_size);
}

// round 13
// speedup vs baseline: 1.2259x; 1.1375x over previous
#include <cuda_runtime.h>
#include <cuda_fp16.h>
#include <cstdint>
#include <math.h>

// ---------------- problem constants ----------------
#define BATCH    64
#define SEQ      32
#define M_TOTAL  2048      // B*T
#define K_TOTAL  32768     // D*H*W
#define N_TOTAL  512       // 4*D
#define N_EXP    9
#define SPLITS   4
#define KCH      64        // K per chunk
#define NCHUNK   128       // chunks per split: 32768/4/64
#define NSTAGE   3
#define NTHREADS 256       // 8 warps: 2 (m) x 4 (n), warp tile 64x64

// A stage: 128 rows x 128B (64 fp16, SW128) = 16384 (STS-only region)
// B stage: 256 rows x 128B (64 fp16, SW128) = 32768 (cp.async-only region)
#define A_STAGE_BYTES 16384
#define STAGE_BYTES   (A_STAGE_BYTES + 32768)
#define SMEM_BYTES    (NSTAGE * STAGE_BYTES + 1024)

// scratch (no allocation allowed -> __device__ globals)
__device__ __half g_Wp[(size_t)N_TOTAL * K_TOTAL];                 // 32 MB fp16, [c][k']
__device__ float  g_scratch[(size_t)SPLITS * M_TOTAL * N_TOTAL];   // 16 MB split-K partials
__device__ float  g_loadpart[BATCH * N_EXP];

// ---------------- helpers ----------------
__device__ __forceinline__ uint32_t smem_u32(const void* p) {
    uint32_t a;
    asm("{ .reg .u64 t; cvta.to.shared.u64 t, %1; cvt.u32.u64 %0, t; }" : "=r"(a) : "l"(p));
    return a;
}
#define SWZ(off) ((off) ^ (((off) >> 3) & 0x70))

__device__ __forceinline__ void cpasync16(uint32_t daddr, const void* src) {
    asm volatile("cp.async.cg.shared.global [%0], [%1], 16;" :: "r"(daddr), "l"(src) : "memory");
}
#define CP_COMMIT() asm volatile("cp.async.commit_group;" ::: "memory")
#define CP_WAIT1()  asm volatile("cp.async.wait_group 1;" ::: "memory")

#define LDSM4(r, addr) \
    asm volatile("ldmatrix.sync.aligned.m8n8.x4.shared.b16 {%0,%1,%2,%3}, [%4];" \
                 : "=r"((r)[0]), "=r"((r)[1]), "=r"((r)[2]), "=r"((r)[3]) : "r"(addr))

#define MMA16816(d, a, b0, b1) \
    asm volatile("mma.sync.aligned.m16n8k16.row.col.f32.f16.f16.f32 " \
                 "{%0,%1,%2,%3}, {%4,%5,%6,%7}, {%8,%9}, {%0,%1,%2,%3};" \
                 : "+f"((d)[0]), "+f"((d)[1]), "+f"((d)[2]), "+f"((d)[3]) \
                 : "r"((a)[0]), "r"((a)[1]), "r"((a)[2]), "r"((a)[3]), "r"(b0), "r"(b1))

__device__ __forceinline__ uint32_t pack2h(float a, float b) {
    uint32_t r;
    asm("cvt.rn.f16x2.f32 %0, %1, %2;" : "=r"(r) : "f"(b), "f"(a));
    return r;
}
__device__ __forceinline__ void sts128(uint32_t addr, uint4 v) {
    asm volatile("st.shared.v4.b32 [%0], {%1, %2, %3, %4};"
                 :: "r"(addr), "r"(v.x), "r"(v.y), "r"(v.z), "r"(v.w) : "memory");
}

// ---------------- no-op kernel (shifts ncu -s window onto k_gemm) ----------------
__global__ void k_nop() {}

// ---------------- kernel 1: permute + convert conv_w -> g_Wp fp16 ----------------
// Wp[c][(h*16+w)*128 + d] = conv_w[c][d][h][w];  d = dblk*16 + j2, dblk in [0,8)
__global__ void __launch_bounds__(256) k_permW(const float* __restrict__ w) {
    int c = blockIdx.x, dblk = blockIdx.y, tid = threadIdx.x;   // grid (512, 8); tid = hw
    const float* src = w + (size_t)c * K_TOTAL + (size_t)dblk * 16 * 256 + tid;
    uint32_t pk[8];
#pragma unroll
    for (int j = 0; j < 8; j++)
        pk[j] = pack2h(src[(2 * j) * 256], src[(2 * j + 1) * 256]);
    __half* dst = g_Wp + (size_t)c * K_TOTAL + (size_t)tid * 128 + dblk * 16;
    reinterpret_cast<uint4*>(dst)[0] = make_uint4(pk[0], pk[1], pk[2], pk[3]);
    reinterpret_cast<uint4*>(dst)[1] = make_uint4(pk[4], pk[5], pk[6], pk[7]);
}

// ---------------- kernel 2: HMMA split-K GEMM ----------------
// grid (16 m-tiles, 2 n-tiles, 4 splits), 256 thr. CTA tile M=128 N=256, K=8192.
// 8 warps: warp_m = wid&1 (64 rows), warp_n = wid>>1 (64 cols).
// A: LDG fp32 -> reg convert -> STS fp16 (2-chunk-ahead pipeline). B: cp.async fp16.

// load A chunk (128 rows x 64 fp32) into 8 float4 regs; unit u = tid + i*256,
// row = u>>3, seg = u&7 (16B-fp16 unit = 8 floats source)
__device__ __forceinline__ void ldgA(float4* r, const float* __restrict__ x,
                                     int m0, int k0, int tid) {
#pragma unroll
    for (int i = 0; i < 4; i++) {
        int u = tid + i * NTHREADS;
        int row = u >> 3, seg = u & 7;
        const float4* s = reinterpret_cast<const float4*>(
            x + (size_t)(m0 + row) * K_TOTAL + k0 + seg * 8);
        r[2 * i]     = s[0];
        r[2 * i + 1] = s[1];
    }
}
__device__ __forceinline__ void stsA(uint32_t sbase, const float4* r, int tid) {
#pragma unroll
    for (int i = 0; i < 4; i++) {
        int u = tid + i * NTHREADS;
        int row = u >> 3, seg = u & 7;
        uint4 v;
        v.x = pack2h(r[2 * i].x,     r[2 * i].y);
        v.y = pack2h(r[2 * i].z,     r[2 * i].w);
        v.z = pack2h(r[2 * i + 1].x, r[2 * i + 1].y);
        v.w = pack2h(r[2 * i + 1].z, r[2 * i + 1].w);
        sts128(sbase + SWZ((uint32_t)row * 128u + (uint32_t)seg * 16u), v);
    }
}
__device__ __forceinline__ void cpasyncB(uint32_t sbase, int n0, int k0, int tid) {
    uint32_t bb = sbase + A_STAGE_BYTES;
#pragma unroll
    for (int i = 0; i < 8; i++) {
        int id = tid + i * NTHREADS;         // 0..2047
        int row = id >> 3, seg = id & 7;
        cpasync16(bb + SWZ((uint32_t)row * 128u + (uint32_t)seg * 16u),
                  g_Wp + (size_t)(n0 + row) * K_TOTAL + k0 + seg * 8);
    }
    CP_COMMIT();
}

__global__ void __launch_bounds__(NTHREADS, 1) k_gemm(const float* __restrict__ x) {
    extern __shared__ char sm[];
    uint32_t ubase = (smem_u32(sm) + 1023u) & ~1023u;

    const int tid = threadIdx.x, lane = tid & 31, wid = tid >> 5;
    const int warp_m = wid & 1, warp_n = wid >> 1;     // 2 x 4 warps, warp tile 64x64
    const int m0 = blockIdx.x * 128, n0 = blockIdx.y * 256;
    const int split = blockIdx.z;
    const int kbase = split * (K_TOTAL / SPLITS);

    float acc[4][8][4];
#pragma unroll
    for (int i = 0; i < 4; i++)
#pragma unroll
        for (int j = 0; j < 8; j++)
#pragma unroll
            for (int q = 0; q < 4; q++) acc[i][j][q] = 0.f;

    // prologue: B stages 0,1 via cp.async; A stage 0 via LDG->STS; prefetch A chunk 1
    cpasyncB(ubase + 0 * STAGE_BYTES, n0, kbase, tid);
    cpasyncB(ubase + 1 * STAGE_BYTES, n0, kbase + KCH, tid);
    float4 xa[8];
    ldgA(xa, x, m0, kbase, tid);
    stsA(ubase + 0 * STAGE_BYTES, xa, tid);
    ldgA(xa, x, m0, kbase + KCH, tid);

    // ldmatrix lane addressing (constant per thread)
    const uint32_t a_row  = (uint32_t)(warp_m * 64 + ((lane >> 3) & 1) * 8 + (lane & 7));
    const uint32_t a_colb = (uint32_t)(((lane >> 4) & 1) * 16);
    const uint32_t b_row  = (uint32_t)(warp_n * 64 + ((lane >> 4) & 1) * 8 + (lane & 7));
    const uint32_t b_colb = (uint32_t)(((lane >> 3) & 1) * 16);

    for (int c = 0; c < NCHUNK; ++c) {
        CP_WAIT1();
        __syncthreads();
        // stage A for chunk c+1 (regs loaded at iter c-1); prefetch A c+2; B c+2
        if (c + 1 < NCHUNK)
            stsA(ubase + ((c + 1) % NSTAGE) * STAGE_BYTES, xa, tid);
        if (c + 2 < NCHUNK) {
            ldgA(xa, x, m0, kbase + (c + 2) * KCH, tid);
            cpasyncB(ubase + ((c + 2) % NSTAGE) * STAGE_BYTES, n0, kbase + (c + 2) * KCH, tid);
        } else {
            CP_COMMIT();   // keep group count constant
        }

        uint32_t As = ubase + (c % NSTAGE) * STAGE_BYTES;
        uint32_t Bs = As + A_STAGE_BYTES;

#pragma unroll
        for (int ks = 0; ks < 4; ks++) {
            uint32_t b[4][4];
#pragma unroll
            for (int nj = 0; nj < 4; nj++)
                LDSM4(b[nj], Bs + SWZ((b_row + nj * 16) * 128u + (uint32_t)(ks * 32) + b_colb));
            uint32_t a2[4][4];
#pragma unroll
            for (int mi = 0; mi < 4; mi++)
                LDSM4(a2[mi], As + SWZ((a_row + mi * 16) * 128u + (uint32_t)(ks * 32) + a_colb));
#pragma unroll
            for (int mi = 0; mi < 4; mi++)
#pragma unroll
                for (int nj = 0; nj < 4; nj++) {
                    MMA16816(acc[mi][2 * nj],     a2[mi], b[nj][0], b[nj][1]);
                    MMA16816(acc[mi][2 * nj + 1], a2[mi], b[nj][2], b[nj][3]);
                }
        }
    }

    // epilogue: write partials to g_scratch[split][m][n]
    float* dst = g_scratch + (size_t)split * M_TOTAL * N_TOTAL;
#pragma unroll
    for (int mi = 0; mi < 4; mi++) {
        int row = m0 + warp_m * 64 + mi * 16 + (lane >> 2);
#pragma unroll
        for (int ni = 0; ni < 8; ni++) {
            int col = n0 + warp_n * 64 + (ni >> 1) * 16 + (ni & 1) * 8 + 2 * (lane & 3);
            *reinterpret_cast<float2*>(dst + (size_t)row * N_TOTAL + col) =
                make_float2(acc[mi][ni][0], acc[mi][ni][1]);
            *reinterpret_cast<float2*>(dst + (size_t)(row + 8) * N_TOTAL + col) =
                make_float2(acc[mi][ni][2], acc[mi][ni][3]);
        }
    }
}

// ---------------- kernel 3: per-batch gating ----------------
__global__ void __launch_bounds__(256) k_gate(
    const float* __restrict__ conv_b, const float* __restrict__ w_gate,
    const float* __restrict__ w_noise, const float* __restrict__ noisev,
    const int* __restrict__ training, float* __restrict__ out, int out_size) {
    extern __shared__ float feat[];            // 32 x 512
    __shared__ float trigc[16][32];
    __shared__ float trigs[16][32];
    __shared__ float wred[16][8];
    __shared__ float amp_s[16];
    int b = blockIdx.x, tid = threadIdx.x;

    for (int idx = tid; idx < 512; idx += 256) {
        int fi = idx >> 5, t = idx & 31;
        float s, c;
        sincospif((float)((fi + 1) * t) / 16.0f, &s, &c);    // angle = 2*pi*f*t/32
        trigc[fi][t] = c;
        trigs[fi][t] = s;
    }

    for (int idx = tid; idx < 32 * 512; idx += 256) {
        int t = idx >> 9, c = idx & 511;
        const float* p = g_scratch + (size_t)(b * 32 + t) * N_TOTAL + c;
        float s = conv_b[c];
#pragma unroll
        for (int sp = 0; sp < SPLITS; sp++) s += p[(size_t)sp * M_TOTAL * N_TOTAL];
        feat[idx] = s;
    }
    __syncthreads();

    float part[16];
#pragma unroll
    for (int f = 0; f < 16; f++) part[f] = 0.f;
#pragma unroll
    for (int cc = 0; cc < 2; cc++) {
        int ch = tid * 2 + cc;
        float v[32];
#pragma unroll
        for (int t = 0; t < 32; t++) v[t] = feat[t * 512 + ch];
#pragma unroll
        for (int f = 0; f < 16; f++) {
            float re = 0.f, im = 0.f;
#pragma unroll
            for (int t = 0; t < 32; t++) {
                re += v[t] * trigc[f][t];
                im += v[t] * trigs[f][t];
            }
            part[f] += sqrtf(re * re + im * im);
        }
    }
    int lane = tid & 31, w = tid >> 5;
#pragma unroll
    for (int f = 0; f < 16; f++) {
        float xv = part[f];
        for (int o = 16; o; o >>= 1) xv += __shfl_down_sync(0xFFFFFFFFu, xv, o);
        if (lane == 0) wred[f][w] = xv;
    }
    __syncthreads();
    if (tid < 16) {
        float s = 0.f;
#pragma unroll
        for (int ww = 0; ww < 8; ww++) s += wred[tid][ww];
        amp_s[tid] = s * (0.17677669529663687f / 512.0f);   // ortho 1/sqrt(32), mean over 512
    }
    __syncthreads();

    if (tid == 0) {
        float amp[16];
        for (int f = 0; f < 16; f++) amp[f] = amp_s[f];
        int tr = training ? (training[0] != 0) : 1;
        float clean[9], lg[9], sd[9];
        for (int e = 0; e < 9; e++) {
            float cg = 0.f, cn = 0.f;
            for (int f = 0; f < 16; f++) {
                cg += amp[f] * w_gate[f * 9 + e];
                cn += amp[f] * w_noise[f * 9 + e];
            }
            clean[e] = cg;
            float sp = (cn > 20.f) ? cn : log1pf(expf(cn));
            sd[e] = sp + 0.01f;
            lg[e] = tr ? (cg + noisev[b * 9 + e] * sd[e]) : cg;
        }
        int i0 = 0, i1 = -1, i2 = -1;
        float v0 = -1e30f, v1 = -1e30f, v2 = -1e30f;
        for (int e = 0; e < 9; e++) if (lg[e] > v0) { v0 = lg[e]; i0 = e; }
        for (int e = 0; e < 9; e++) if (e != i0 && lg[e] > v1) { v1 = lg[e]; i1 = e; }
        for (int e = 0; e < 9; e++) if (e != i0 && e != i1 && lg[e] > v2) { v2 = lg[e]; i2 = e; }
        float e1 = expf(v1 - v0);
        float inv = 1.f / (1.f + e1);
        if (b * 9 + 9 <= out_size) {
            for (int e = 0; e < 9; e++) out[b * 9 + e] = 0.f;
            out[b * 9 + i0] = inv;
            out[b * 9 + i1] = e1 * inv;
        }
        if (tr) {
            for (int e = 0; e < 9; e++) {
                float thr = (lg[e] > v2) ? v2 : v1;
                float xn = (clean[e] - thr) / sd[e];
                g_loadpart[b * 9 + e] = 0.5f * erfcf(-xn * 0.7071067811865476f);
            }
        } else {
            for (int e = 0; e < 9; e++)
                g_loadpart[b * 9 + e] = (e == i0 || e == i1) ? 1.f : 0.f;
        }
        (void)i2;
    }
}

// ---------------- kernel 4: deterministic load reduction ----------------
__global__ void k_load(float* __restrict__ out, int out_size) {
    int e = threadIdx.x;
    if (e < N_EXP && BATCH * N_EXP + e < out_size) {
        float s = 0.f;
        for (int b = 0; b < BATCH; b++) s += g_loadpart[b * N_EXP + e];
        out[BATCH * N_EXP + e] = s;
    }
}

// ---------------- launch ----------------
extern "C" void kernel_launch(void* const* d_in, const int* in_sizes, int n_in,
                              void* d_out, int out_size) {
    const float* x       = (const float*)d_in[0];
    const float* conv_w  = (const float*)d_in[1];
    const float* conv_b  = (const float*)d_in[2];
    const float* w_gate  = (const float*)d_in[3];
    const float* w_noise = (const float*)d_in[4];
    const float* noisev  = (const float*)d_in[5];
    const int*   training = (n_in > 6) ? (const int*)d_in[6] : nullptr;
    float* out = (float*)d_out;

    cudaFuncSetAttribute(k_gemm, cudaFuncAttributeMaxDynamicSharedMemorySize, SMEM_BYTES);
    cudaFuncSetAttribute(k_gate, cudaFuncAttributeMaxDynamicSharedMemorySize, 65536);

    k_permW<<<dim3(512, 8), 256>>>(conv_w);
    k_nop<<<1, 32>>>();   // ncu -s alignment: keep k_gemm as 4th app launch
    k_nop<<<1, 32>>>();
    k_gemm<<<dim3(16, 2, SPLITS), NTHREADS, SMEM_BYTES>>>(x);
    k_gate<<<BATCH, 256, 65536>>>(conv_b, w_gate, w_noise, noisev, training, out, out_size);
    k_load<<<1, 32>>>(out, out_size);
}